// round 1
// baseline (speedup 1.0000x reference)
#include <cuda_runtime.h>
#include <cuda_bf16.h>
#include <cstdint>

// ---------------- problem constants ----------------
#define D_MODEL 1024
#define N_HEADS 16
#define D_HEAD  64
#define LATENT  32
#define T_SEQ   4096
#define NEG_INF (-1e9f)

// ---------------- device scratch (no allocs allowed) ----------------
// B=2 fixed by the dataset; sized for B*T = 8192 rows.
#define MAX_BT 8192
__device__ float g_lat[MAX_BT * LATENT];        // 1 MB
__device__ float g_K  [MAX_BT * D_MODEL];       // 32 MB
__device__ float g_V  [MAX_BT * D_MODEL];       // 32 MB
__device__ float g_Q  [MAX_BT * D_MODEL];       // 32 MB
__device__ float g_O  [MAX_BT * D_MODEL];       // 32 MB

// =====================================================================
// Kernel 1: lat = x @ W_kv   [BT,1024] x [1024,32] -> [BT,32]
// block = 256 threads = 8 row-groups x 32 cols, 4 rows per thread
// =====================================================================
__global__ void lat_kernel(const float* __restrict__ x,
                           const float* __restrict__ Wkv,
                           float* __restrict__ lat) {
    int col = threadIdx.x & 31;
    int rg  = threadIdx.x >> 5;                 // 0..7
    int row0 = blockIdx.x * 32 + rg * 4;
    float acc0 = 0.f, acc1 = 0.f, acc2 = 0.f, acc3 = 0.f;
    const float* x0 = x + (size_t)row0 * D_MODEL;
    const float* x1 = x0 + D_MODEL;
    const float* x2 = x1 + D_MODEL;
    const float* x3 = x2 + D_MODEL;
#pragma unroll 4
    for (int k = 0; k < D_MODEL; k++) {
        float w = __ldg(Wkv + k * LATENT + col);
        acc0 += x0[k] * w;
        acc1 += x1[k] * w;
        acc2 += x2[k] * w;
        acc3 += x3[k] * w;
    }
    lat[(size_t)(row0 + 0) * LATENT + col] = acc0;
    lat[(size_t)(row0 + 1) * LATENT + col] = acc1;
    lat[(size_t)(row0 + 2) * LATENT + col] = acc2;
    lat[(size_t)(row0 + 3) * LATENT + col] = acc3;
}

// =====================================================================
// Kernel 2: K = lat @ W_k ; V = lat @ W_v   [BT,32] x [32,1024]
// block handles 4 bt rows; 256 threads each own 4 output cols (float4)
// =====================================================================
__global__ void kv_kernel(const float* __restrict__ lat,
                          const float* __restrict__ Wk,
                          const float* __restrict__ Wv,
                          float* __restrict__ K,
                          float* __restrict__ V) {
    __shared__ float ls[4][LATENT];
    int bt0 = blockIdx.x * 4;
    if (threadIdx.x < 4 * LATENT) {
        int r = threadIdx.x / LATENT, l = threadIdx.x % LATENT;
        ls[r][l] = lat[(size_t)(bt0 + r) * LATENT + l];
    }
    __syncthreads();
    int c0 = threadIdx.x * 4;
    float4 ak[4], av[4];
#pragma unroll
    for (int r = 0; r < 4; r++) { ak[r] = make_float4(0,0,0,0); av[r] = make_float4(0,0,0,0); }
#pragma unroll 4
    for (int l = 0; l < LATENT; l++) {
        float4 wk = *(const float4*)(Wk + (size_t)l * D_MODEL + c0);
        float4 wv = *(const float4*)(Wv + (size_t)l * D_MODEL + c0);
#pragma unroll
        for (int r = 0; r < 4; r++) {
            float lv = ls[r][l];
            ak[r].x += lv * wk.x; ak[r].y += lv * wk.y; ak[r].z += lv * wk.z; ak[r].w += lv * wk.w;
            av[r].x += lv * wv.x; av[r].y += lv * wv.y; av[r].z += lv * wv.z; av[r].w += lv * wv.w;
        }
    }
#pragma unroll
    for (int r = 0; r < 4; r++) {
        *(float4*)(K + (size_t)(bt0 + r) * D_MODEL + c0) = ak[r];
        *(float4*)(V + (size_t)(bt0 + r) * D_MODEL + c0) = av[r];
    }
}

// =====================================================================
// Kernel 3/5: SGEMM C[M,N] = A[M,K] @ B[K,N], all row-major fp32.
// 128x128x8 tiles, 256 threads, 8x8 per-thread microtile.
// M%128==0, N%128==0, K%8==0 assumed (8192/1024/1024).
// =====================================================================
__global__ __launch_bounds__(256, 2)
void sgemm_kernel(const float* __restrict__ A,
                  const float* __restrict__ B,
                  float* __restrict__ C,
                  int M, int N, int K) {
    __shared__ float As[8][128];
    __shared__ float Bs[8][128];
    const int tid = threadIdx.x;
    const int bm = blockIdx.y * 128;
    const int bn = blockIdx.x * 128;
    const int tx = tid & 15;         // 0..15  -> col block of 8
    const int ty = tid >> 4;         // 0..15  -> row block of 8

    const int a_row = tid >> 1;           // 0..127
    const int a_col = (tid & 1) * 4;      // 0 or 4
    const int b_row = tid >> 5;           // 0..7
    const int b_col = (tid & 31) * 4;     // 0..124

    float acc[8][8];
#pragma unroll
    for (int i = 0; i < 8; i++)
#pragma unroll
        for (int j = 0; j < 8; j++) acc[i][j] = 0.f;

    for (int k0 = 0; k0 < K; k0 += 8) {
        float4 avd = *(const float4*)(A + (size_t)(bm + a_row) * K + k0 + a_col);
        As[a_col + 0][a_row] = avd.x;
        As[a_col + 1][a_row] = avd.y;
        As[a_col + 2][a_row] = avd.z;
        As[a_col + 3][a_row] = avd.w;
        float4 bvd = *(const float4*)(B + (size_t)(k0 + b_row) * N + bn + b_col);
        *(float4*)(&Bs[b_row][b_col]) = bvd;
        __syncthreads();
#pragma unroll
        for (int kk = 0; kk < 8; kk++) {
            float ar[8], br[8];
            float4 a0 = *(const float4*)(&As[kk][ty * 8]);
            float4 a1 = *(const float4*)(&As[kk][ty * 8 + 4]);
            float4 b0 = *(const float4*)(&Bs[kk][tx * 8]);
            float4 b1 = *(const float4*)(&Bs[kk][tx * 8 + 4]);
            ar[0]=a0.x; ar[1]=a0.y; ar[2]=a0.z; ar[3]=a0.w;
            ar[4]=a1.x; ar[5]=a1.y; ar[6]=a1.z; ar[7]=a1.w;
            br[0]=b0.x; br[1]=b0.y; br[2]=b0.z; br[3]=b0.w;
            br[4]=b1.x; br[5]=b1.y; br[6]=b1.z; br[7]=b1.w;
#pragma unroll
            for (int i = 0; i < 8; i++)
#pragma unroll
                for (int j = 0; j < 8; j++)
                    acc[i][j] += ar[i] * br[j];
        }
        __syncthreads();
    }
#pragma unroll
    for (int i = 0; i < 8; i++) {
        float* crow = C + (size_t)(bm + ty * 8 + i) * N + bn + tx * 8;
        *(float4*)(crow)     = make_float4(acc[i][0], acc[i][1], acc[i][2], acc[i][3]);
        *(float4*)(crow + 4) = make_float4(acc[i][4], acc[i][5], acc[i][6], acc[i][7]);
    }
}

// =====================================================================
// Kernel 4: causal flash attention, fp32.
// One block = one (b,h, 64-row q tile). 256 threads, 4x4 microtiles.
// Layouts: Q/K/V/O flat [B*T, H*dh] with head h at cols h*64..h*64+63.
// Q tile cached in smem d-major; per k-tile: S=Q·K^T, online softmax, P·V.
// =====================================================================
#define ATP 68   // padded row length (float4-aligned, odd/4 for bank spread)
__global__ __launch_bounds__(256)
void attn_kernel(const float* __restrict__ Q,
                 const float* __restrict__ K,
                 const float* __restrict__ V,
                 float* __restrict__ O,
                 int T) {
    extern __shared__ float sm[];
    float* Qt = sm;                 // [64][ATP]  Qt[d][q]
    float* Kt = Qt + 64 * ATP;      // [64][ATP]  Kt[d][k]
    float* Ps = Kt + 64 * ATP;      // [64][ATP]  Ps[q][k]
    float* Vs = Ps + 64 * ATP;      // [64][64]   Vs[k][d]

    const int qt = (gridDim.x - 1) - blockIdx.x;   // heavy tiles first
    const int bh = blockIdx.y;
    const int b  = bh >> 4;
    const int h  = bh & 15;
    const int tid = threadIdx.x;
    const int tx = tid & 15;    // k/d col group
    const int ty = tid >> 4;    // q row group
    const float scale = 0.125f; // 1/sqrt(64)

    const size_t base = ((size_t)b * T) * D_MODEL + h * D_HEAD;

    // load Q tile (transposed into smem)
    for (int i = tid; i < 64 * 64; i += 256) {
        int q = i >> 6, d = i & 63;
        Qt[d * ATP + q] = Q[base + (size_t)(qt * 64 + q) * D_MODEL + d];
    }

    float m[4], l[4], acc[4][4];
#pragma unroll
    for (int i = 0; i < 4; i++) {
        m[i] = -1e30f; l[i] = 0.f;
#pragma unroll
        for (int j = 0; j < 4; j++) acc[i][j] = 0.f;
    }

    for (int kt = 0; kt <= qt; kt++) {
        __syncthreads();  // previous P·V done before overwriting Kt/Vs
        for (int i = tid; i < 64 * 64; i += 256) {
            int k = i >> 6, d = i & 63;
            size_t gidx = base + (size_t)(kt * 64 + k) * D_MODEL + d;
            Kt[d * ATP + k] = K[gidx];
            Vs[k * 64 + d]  = V[gidx];
        }
        __syncthreads();

        // S = Q·K^T (4x4 per thread)
        float s[4][4];
#pragma unroll
        for (int i = 0; i < 4; i++)
#pragma unroll
            for (int j = 0; j < 4; j++) s[i][j] = 0.f;
#pragma unroll 4
        for (int d = 0; d < 64; d++) {
            float4 qv = *(const float4*)(&Qt[d * ATP + ty * 4]);
            float4 kv = *(const float4*)(&Kt[d * ATP + tx * 4]);
            float qa[4] = {qv.x, qv.y, qv.z, qv.w};
            float ka[4] = {kv.x, kv.y, kv.z, kv.w};
#pragma unroll
            for (int i = 0; i < 4; i++)
#pragma unroll
                for (int j = 0; j < 4; j++)
                    s[i][j] += qa[i] * ka[j];
        }

        const bool diag = (kt == qt);
#pragma unroll
        for (int i = 0; i < 4; i++) {
#pragma unroll
            for (int j = 0; j < 4; j++) {
                s[i][j] *= scale;
                if (diag && (tx * 4 + j) > (ty * 4 + i)) s[i][j] += NEG_INF;
            }
        }

        // online softmax per q-row (reduce across 16 tx lanes in half-warp)
#pragma unroll
        for (int i = 0; i < 4; i++) {
            float rm = fmaxf(fmaxf(s[i][0], s[i][1]), fmaxf(s[i][2], s[i][3]));
#pragma unroll
            for (int off = 8; off >= 1; off >>= 1)
                rm = fmaxf(rm, __shfl_xor_sync(0xffffffffu, rm, off));
            float mnew = fmaxf(m[i], rm);
            float corr = __expf(m[i] - mnew);
            float rs = 0.f;
#pragma unroll
            for (int j = 0; j < 4; j++) {
                s[i][j] = __expf(s[i][j] - mnew);
                rs += s[i][j];
            }
#pragma unroll
            for (int off = 8; off >= 1; off >>= 1)
                rs += __shfl_xor_sync(0xffffffffu, rs, off);
            l[i] = l[i] * corr + rs;
            m[i] = mnew;
#pragma unroll
            for (int j = 0; j < 4; j++) acc[i][j] *= corr;
            // stash P row chunk
            *(float4*)(&Ps[(ty * 4 + i) * ATP + tx * 4]) =
                make_float4(s[i][0], s[i][1], s[i][2], s[i][3]);
        }
        __syncthreads();

        // O += P · V  (k-loop)
#pragma unroll 4
        for (int k = 0; k < 64; k++) {
            float pv[4];
#pragma unroll
            for (int i = 0; i < 4; i++) pv[i] = Ps[(ty * 4 + i) * ATP + k];
            float4 vv = *(const float4*)(&Vs[k * 64 + tx * 4]);
            float va[4] = {vv.x, vv.y, vv.z, vv.w};
#pragma unroll
            for (int i = 0; i < 4; i++)
#pragma unroll
                for (int j = 0; j < 4; j++)
                    acc[i][j] += pv[i] * va[j];
        }
    }

    // epilogue: normalize and store
#pragma unroll
    for (int i = 0; i < 4; i++) {
        float inv = 1.f / l[i];
        float* orow = O + base + (size_t)(qt * 64 + ty * 4 + i) * D_MODEL + tx * 4;
        *(float4*)orow = make_float4(acc[i][0] * inv, acc[i][1] * inv,
                                     acc[i][2] * inv, acc[i][3] * inv);
    }
}

// =====================================================================
// launch
// =====================================================================
extern "C" void kernel_launch(void* const* d_in, const int* in_sizes, int n_in,
                              void* d_out, int out_size) {
    const float* x    = (const float*)d_in[0];
    const float* W_kv = (const float*)d_in[1];
    const float* W_k  = (const float*)d_in[2];
    const float* W_v  = (const float*)d_in[3];
    const float* W_q  = (const float*)d_in[4];
    const float* W_o  = (const float*)d_in[5];
    float* out = (float*)d_out;

    const int BT = in_sizes[0] / D_MODEL;   // 8192
    const int T  = T_SEQ;                   // 4096
    const int B  = BT / T;                  // 2

    float *lat, *Kf, *Vf, *Qf, *Of;
    cudaGetSymbolAddress((void**)&lat, g_lat);
    cudaGetSymbolAddress((void**)&Kf,  g_K);
    cudaGetSymbolAddress((void**)&Vf,  g_V);
    cudaGetSymbolAddress((void**)&Qf,  g_Q);
    cudaGetSymbolAddress((void**)&Of,  g_O);

    // attention smem: 3*64*68 + 64*64 floats
    const int attn_smem = (3 * 64 * ATP + 64 * 64) * (int)sizeof(float);
    cudaFuncSetAttribute(attn_kernel, cudaFuncAttributeMaxDynamicSharedMemorySize,
                         attn_smem);

    // 1. lat = x @ W_kv
    lat_kernel<<<BT / 32, 256>>>(x, W_kv, lat);

    // 2. K,V = lat @ W_k / W_v
    kv_kernel<<<BT / 4, 256>>>(lat, W_k, W_v, Kf, Vf);

    // 3. Q = x @ W_q
    dim3 gq(D_MODEL / 128, BT / 128);
    sgemm_kernel<<<gq, 256>>>(x, W_q, Qf, BT, D_MODEL, D_MODEL);

    // 4. causal flash attention
    dim3 ga(T / 64, B * N_HEADS);
    attn_kernel<<<ga, 256, attn_smem>>>(Qf, Kf, Vf, Of, T);

    // 5. out = O @ W_o
    sgemm_kernel<<<gq, 256>>>(Of, W_o, out, BT, D_MODEL, D_MODEL);
}

// round 2
// speedup vs baseline: 2.4106x; 2.4106x over previous
#include <cuda_runtime.h>
#include <cuda_bf16.h>
#include <cstdint>

// ---------------- problem constants ----------------
#define D_MODEL 1024
#define N_HEADS 16
#define D_HEAD  64
#define LATENT  32
#define T_SEQ   4096
#define NEG_INF (-1e9f)

// ---------------- device scratch (no allocs allowed) ----------------
#define MAX_BT 8192
__device__ float g_lat[MAX_BT * LATENT];
__device__ float g_K  [MAX_BT * D_MODEL];
__device__ float g_V  [MAX_BT * D_MODEL];
__device__ float g_Q  [MAX_BT * D_MODEL];
__device__ float g_O  [MAX_BT * D_MODEL];

// ---------------- tf32 mma helpers ----------------
__device__ __forceinline__ float f2tf(float f) {
    uint32_t u;
    asm("cvt.rna.tf32.f32 %0, %1;" : "=r"(u) : "f"(f));
    return __uint_as_float(u);
}
__device__ __forceinline__ void mma_tf32(float c[4],
                                         uint32_t a0, uint32_t a1, uint32_t a2, uint32_t a3,
                                         uint32_t b0, uint32_t b1) {
    asm volatile(
        "mma.sync.aligned.m16n8k8.row.col.f32.tf32.tf32.f32 "
        "{%0,%1,%2,%3},{%4,%5,%6,%7},{%8,%9},{%0,%1,%2,%3};"
        : "+f"(c[0]), "+f"(c[1]), "+f"(c[2]), "+f"(c[3])
        : "r"(a0), "r"(a1), "r"(a2), "r"(a3), "r"(b0), "r"(b1));
}

// =====================================================================
// Kernel 1: lat = x @ W_kv   [BT,1024] x [1024,32] -> [BT,32]  (fp32 exact)
// =====================================================================
__global__ void lat_kernel(const float* __restrict__ x,
                           const float* __restrict__ Wkv,
                           float* __restrict__ lat) {
    int col = threadIdx.x & 31;
    int rg  = threadIdx.x >> 5;
    int row0 = blockIdx.x * 32 + rg * 4;
    float acc0 = 0.f, acc1 = 0.f, acc2 = 0.f, acc3 = 0.f;
    const float* x0 = x + (size_t)row0 * D_MODEL;
    const float* x1 = x0 + D_MODEL;
    const float* x2 = x1 + D_MODEL;
    const float* x3 = x2 + D_MODEL;
#pragma unroll 4
    for (int k = 0; k < D_MODEL; k++) {
        float w = __ldg(Wkv + k * LATENT + col);
        acc0 += x0[k] * w;
        acc1 += x1[k] * w;
        acc2 += x2[k] * w;
        acc3 += x3[k] * w;
    }
    lat[(size_t)(row0 + 0) * LATENT + col] = acc0;
    lat[(size_t)(row0 + 1) * LATENT + col] = acc1;
    lat[(size_t)(row0 + 2) * LATENT + col] = acc2;
    lat[(size_t)(row0 + 3) * LATENT + col] = acc3;
}

// =====================================================================
// Kernel 2: K = lat @ W_k ; V = lat @ W_v   (fp32 exact)
// =====================================================================
__global__ void kv_kernel(const float* __restrict__ lat,
                          const float* __restrict__ Wk,
                          const float* __restrict__ Wv,
                          float* __restrict__ K,
                          float* __restrict__ V) {
    __shared__ float ls[4][LATENT];
    int bt0 = blockIdx.x * 4;
    if (threadIdx.x < 4 * LATENT) {
        int r = threadIdx.x / LATENT, l = threadIdx.x % LATENT;
        ls[r][l] = lat[(size_t)(bt0 + r) * LATENT + l];
    }
    __syncthreads();
    int c0 = threadIdx.x * 4;
    float4 ak[4], av[4];
#pragma unroll
    for (int r = 0; r < 4; r++) { ak[r] = make_float4(0,0,0,0); av[r] = make_float4(0,0,0,0); }
#pragma unroll 4
    for (int l = 0; l < LATENT; l++) {
        float4 wk = *(const float4*)(Wk + (size_t)l * D_MODEL + c0);
        float4 wv = *(const float4*)(Wv + (size_t)l * D_MODEL + c0);
#pragma unroll
        for (int r = 0; r < 4; r++) {
            float lv = ls[r][l];
            ak[r].x += lv * wk.x; ak[r].y += lv * wk.y; ak[r].z += lv * wk.z; ak[r].w += lv * wk.w;
            av[r].x += lv * wv.x; av[r].y += lv * wv.y; av[r].z += lv * wv.z; av[r].w += lv * wv.w;
        }
    }
#pragma unroll
    for (int r = 0; r < 4; r++) {
        *(float4*)(K + (size_t)(bt0 + r) * D_MODEL + c0) = ak[r];
        *(float4*)(V + (size_t)(bt0 + r) * D_MODEL + c0) = av[r];
    }
}

// =====================================================================
// Kernel 3/5: tf32 MMA GEMM  C[M,N] = A[M,K] @ B[K,N]  (row-major fp32 io)
// 128x128 block tile, k-chunk 16, 256 threads = 8 warps (2x4), warp 64x32.
// =====================================================================
#define GAP 20    // As row stride (floats): conflict-free A frags
#define GBP 136   // Bs row stride (floats): conflict-free B frags
__global__ __launch_bounds__(256, 2)
void gemm_tf32(const float* __restrict__ A,
               const float* __restrict__ B,
               float* __restrict__ C,
               int M, int N, int K) {
    __shared__ float As[128 * GAP];
    __shared__ float Bs[16 * GBP];
    const int tid = threadIdx.x;
    const int lane = tid & 31;
    const int wid = tid >> 5;
    const int bm = blockIdx.y * 128;
    const int bn = blockIdx.x * 128;
    const int wm = (wid >> 2) * 64;
    const int wn = (wid & 3) * 32;
    const int lq = lane >> 2;   // 0..7
    const int lr = lane & 3;    // 0..3

    float acc[4][4][4];
#pragma unroll
    for (int mt = 0; mt < 4; mt++)
#pragma unroll
        for (int nt = 0; nt < 4; nt++)
#pragma unroll
            for (int j = 0; j < 4; j++) acc[mt][nt][j] = 0.f;

    for (int k0 = 0; k0 < K; k0 += 16) {
        // A: 128x16 -> As (tf32)
#pragma unroll
        for (int i = 0; i < 2; i++) {
            int idx = tid + i * 256;          // 0..511
            int row = idx >> 2;
            int c4  = (idx & 3) * 4;
            float4 v = *(const float4*)(A + (size_t)(bm + row) * K + k0 + c4);
            *(float4*)(&As[row * GAP + c4]) =
                make_float4(f2tf(v.x), f2tf(v.y), f2tf(v.z), f2tf(v.w));
        }
        // B: 16x128 -> Bs (tf32)
#pragma unroll
        for (int i = 0; i < 2; i++) {
            int idx = tid + i * 256;
            int row = idx >> 5;
            int c4  = (idx & 31) * 4;
            float4 v = *(const float4*)(B + (size_t)(k0 + row) * N + bn + c4);
            *(float4*)(&Bs[row * GBP + c4]) =
                make_float4(f2tf(v.x), f2tf(v.y), f2tf(v.z), f2tf(v.w));
        }
        __syncthreads();

#pragma unroll
        for (int kk = 0; kk < 16; kk += 8) {
            uint32_t a[4][4];
#pragma unroll
            for (int mt = 0; mt < 4; mt++) {
                int r = wm + mt * 16 + lq;
                a[mt][0] = __float_as_uint(As[r * GAP + kk + lr]);
                a[mt][1] = __float_as_uint(As[(r + 8) * GAP + kk + lr]);
                a[mt][2] = __float_as_uint(As[r * GAP + kk + lr + 4]);
                a[mt][3] = __float_as_uint(As[(r + 8) * GAP + kk + lr + 4]);
            }
#pragma unroll
            for (int nt = 0; nt < 4; nt++) {
                uint32_t b0 = __float_as_uint(Bs[(kk + lr) * GBP + wn + nt * 8 + lq]);
                uint32_t b1 = __float_as_uint(Bs[(kk + lr + 4) * GBP + wn + nt * 8 + lq]);
#pragma unroll
                for (int mt = 0; mt < 4; mt++)
                    mma_tf32(acc[mt][nt], a[mt][0], a[mt][1], a[mt][2], a[mt][3], b0, b1);
            }
        }
        __syncthreads();
    }

#pragma unroll
    for (int mt = 0; mt < 4; mt++) {
        int r0 = bm + wm + mt * 16 + lq;
#pragma unroll
        for (int nt = 0; nt < 4; nt++) {
            int col = bn + wn + nt * 8 + 2 * lr;
            *(float2*)(C + (size_t)r0 * N + col)       = make_float2(acc[mt][nt][0], acc[mt][nt][1]);
            *(float2*)(C + (size_t)(r0 + 8) * N + col) = make_float2(acc[mt][nt][2], acc[mt][nt][3]);
        }
    }
}

// =====================================================================
// Kernel 4: causal flash attention, tf32 MMA.
// Block: 256 thr (8 warps), q-tile 128, k-tile 64, dh=64.
// Warp w owns q rows [16w, 16w+16). Layouts flat [B*T, H*dh].
// =====================================================================
#define AP 68   // smem row stride (floats) -> conflict-free fragment loads
__global__ __launch_bounds__(256, 2)
void attn_kernel(const float* __restrict__ Q,
                 const float* __restrict__ K,
                 const float* __restrict__ V,
                 float* __restrict__ O,
                 int T) {
    extern __shared__ float sm[];
    float* Qs = sm;                 // [128][AP]  Qs[q][d]
    float* Ks = Qs + 128 * AP;      // [64][AP]   Ks[k][d]
    float* Vs = Ks + 64 * AP;       // [64][AP]   Vs[k][d]
    float* Ps = Vs + 64 * AP;       // [128][AP]  Ps[q][k]

    const int qt  = (gridDim.x - 1) - blockIdx.x;   // heavy tiles first
    const int bh  = blockIdx.y;
    const int b   = bh >> 4;
    const int h   = bh & 15;
    const int tid = threadIdx.x;
    const int wid = tid >> 5;
    const int lane = tid & 31;
    const int lq = lane >> 2;    // 0..7
    const int lr = lane & 3;     // 0..3
    const float scale = 0.125f;  // 1/sqrt(64)

    const size_t base = ((size_t)b * T) * D_MODEL + (size_t)h * D_HEAD;

    // load Q tile [128 x 64] (tf32)
#pragma unroll
    for (int i = tid; i < 128 * 16; i += 256) {
        int q = i >> 4, c4 = (i & 15) * 4;
        float4 v = *(const float4*)(Q + base + (size_t)(qt * 128 + q) * D_MODEL + c4);
        *(float4*)(&Qs[q * AP + c4]) =
            make_float4(f2tf(v.x), f2tf(v.y), f2tf(v.z), f2tf(v.w));
    }

    float oacc[8][4];
#pragma unroll
    for (int dt = 0; dt < 8; dt++)
#pragma unroll
        for (int j = 0; j < 4; j++) oacc[dt][j] = 0.f;
    float m0 = -1e30f, m1 = -1e30f, l0 = 0.f, l1 = 0.f;

    const int gq0 = qt * 128 + wid * 16 + lq;
    const int gq1 = gq0 + 8;
    const int kt_max = 2 * qt + 1;

    for (int kt = 0; kt <= kt_max; kt++) {
        __syncthreads();
        // load K,V tiles [64 x 64] (tf32)
#pragma unroll
        for (int i = tid; i < 64 * 16; i += 256) {
            int k = i >> 4, c4 = (i & 15) * 4;
            size_t g = base + (size_t)(kt * 64 + k) * D_MODEL + c4;
            float4 kv4 = *(const float4*)(K + g);
            float4 vv4 = *(const float4*)(V + g);
            *(float4*)(&Ks[k * AP + c4]) =
                make_float4(f2tf(kv4.x), f2tf(kv4.y), f2tf(kv4.z), f2tf(kv4.w));
            *(float4*)(&Vs[k * AP + c4]) =
                make_float4(f2tf(vv4.x), f2tf(vv4.y), f2tf(vv4.z), f2tf(vv4.w));
        }
        __syncthreads();

        // ---- S = Q K^T : warp computes 16 x 64 ----
        float sacc[8][4];
#pragma unroll
        for (int n = 0; n < 8; n++)
#pragma unroll
            for (int j = 0; j < 4; j++) sacc[n][j] = 0.f;

#pragma unroll
        for (int kk = 0; kk < 8; kk++) {
            int r = wid * 16 + lq;
            uint32_t a0 = __float_as_uint(Qs[r * AP + kk * 8 + lr]);
            uint32_t a1 = __float_as_uint(Qs[(r + 8) * AP + kk * 8 + lr]);
            uint32_t a2 = __float_as_uint(Qs[r * AP + kk * 8 + lr + 4]);
            uint32_t a3 = __float_as_uint(Qs[(r + 8) * AP + kk * 8 + lr + 4]);
#pragma unroll
            for (int n = 0; n < 8; n++) {
                uint32_t b0 = __float_as_uint(Ks[(n * 8 + lq) * AP + kk * 8 + lr]);
                uint32_t b1 = __float_as_uint(Ks[(n * 8 + lq) * AP + kk * 8 + lr + 4]);
                mma_tf32(sacc[n], a0, a1, a2, a3, b0, b1);
            }
        }

        // ---- scale + causal mask ----
        const bool needmask = (kt >= 2 * qt);
#pragma unroll
        for (int n = 0; n < 8; n++) {
#pragma unroll
            for (int j = 0; j < 4; j++) {
                float v = sacc[n][j] * scale;
                if (needmask) {
                    int gk = kt * 64 + n * 8 + 2 * lr + (j & 1);
                    int gq = (j < 2) ? gq0 : gq1;
                    if (gk > gq) v += NEG_INF;
                }
                sacc[n][j] = v;
            }
        }

        // ---- online softmax (rows r0, r1 per thread) ----
        float mx0 = -1e30f, mx1 = -1e30f;
#pragma unroll
        for (int n = 0; n < 8; n++) {
            mx0 = fmaxf(mx0, fmaxf(sacc[n][0], sacc[n][1]));
            mx1 = fmaxf(mx1, fmaxf(sacc[n][2], sacc[n][3]));
        }
        mx0 = fmaxf(mx0, __shfl_xor_sync(0xffffffffu, mx0, 1));
        mx0 = fmaxf(mx0, __shfl_xor_sync(0xffffffffu, mx0, 2));
        mx1 = fmaxf(mx1, __shfl_xor_sync(0xffffffffu, mx1, 1));
        mx1 = fmaxf(mx1, __shfl_xor_sync(0xffffffffu, mx1, 2));
        float mn0 = fmaxf(m0, mx0);
        float mn1 = fmaxf(m1, mx1);
        float c0 = __expf(m0 - mn0);
        float c1 = __expf(m1 - mn1);
        float s0 = 0.f, s1 = 0.f;
#pragma unroll
        for (int n = 0; n < 8; n++) {
            sacc[n][0] = __expf(sacc[n][0] - mn0);
            sacc[n][1] = __expf(sacc[n][1] - mn0);
            sacc[n][2] = __expf(sacc[n][2] - mn1);
            sacc[n][3] = __expf(sacc[n][3] - mn1);
            s0 += sacc[n][0] + sacc[n][1];
            s1 += sacc[n][2] + sacc[n][3];
        }
        s0 += __shfl_xor_sync(0xffffffffu, s0, 1);
        s0 += __shfl_xor_sync(0xffffffffu, s0, 2);
        s1 += __shfl_xor_sync(0xffffffffu, s1, 1);
        s1 += __shfl_xor_sync(0xffffffffu, s1, 2);
        l0 = l0 * c0 + s0;
        l1 = l1 * c1 + s1;
        m0 = mn0; m1 = mn1;
#pragma unroll
        for (int dt = 0; dt < 8; dt++) {
            oacc[dt][0] *= c0; oacc[dt][1] *= c0;
            oacc[dt][2] *= c1; oacc[dt][3] *= c1;
        }

        // ---- P -> smem (tf32), own warp rows only ----
        {
            int r0 = wid * 16 + lq;
#pragma unroll
            for (int n = 0; n < 8; n++) {
                int col = n * 8 + 2 * lr;
                *(float2*)(&Ps[r0 * AP + col]) =
                    make_float2(f2tf(sacc[n][0]), f2tf(sacc[n][1]));
                *(float2*)(&Ps[(r0 + 8) * AP + col]) =
                    make_float2(f2tf(sacc[n][2]), f2tf(sacc[n][3]));
            }
        }
        __syncwarp();

        // ---- O += P V : warp 16 x 64 ----
#pragma unroll
        for (int kk = 0; kk < 8; kk++) {
            int r = wid * 16 + lq;
            uint32_t a0 = __float_as_uint(Ps[r * AP + kk * 8 + lr]);
            uint32_t a1 = __float_as_uint(Ps[(r + 8) * AP + kk * 8 + lr]);
            uint32_t a2 = __float_as_uint(Ps[r * AP + kk * 8 + lr + 4]);
            uint32_t a3 = __float_as_uint(Ps[(r + 8) * AP + kk * 8 + lr + 4]);
#pragma unroll
            for (int dt = 0; dt < 8; dt++) {
                uint32_t b0 = __float_as_uint(Vs[(kk * 8 + lr) * AP + dt * 8 + lq]);
                uint32_t b1 = __float_as_uint(Vs[(kk * 8 + lr + 4) * AP + dt * 8 + lq]);
                mma_tf32(oacc[dt], a0, a1, a2, a3, b0, b1);
            }
        }
    }

    // ---- epilogue ----
    float inv0 = 1.f / l0;
    float inv1 = 1.f / l1;
#pragma unroll
    for (int dt = 0; dt < 8; dt++) {
        int col = dt * 8 + 2 * lr;
        *(float2*)(O + base + (size_t)gq0 * D_MODEL + col) =
            make_float2(oacc[dt][0] * inv0, oacc[dt][1] * inv0);
        *(float2*)(O + base + (size_t)gq1 * D_MODEL + col) =
            make_float2(oacc[dt][2] * inv1, oacc[dt][3] * inv1);
    }
}

// =====================================================================
// launch
// =====================================================================
extern "C" void kernel_launch(void* const* d_in, const int* in_sizes, int n_in,
                              void* d_out, int out_size) {
    const float* x    = (const float*)d_in[0];
    const float* W_kv = (const float*)d_in[1];
    const float* W_k  = (const float*)d_in[2];
    const float* W_v  = (const float*)d_in[3];
    const float* W_q  = (const float*)d_in[4];
    const float* W_o  = (const float*)d_in[5];
    float* out = (float*)d_out;

    const int BT = in_sizes[0] / D_MODEL;   // 8192
    const int T  = T_SEQ;                   // 4096
    const int B  = BT / T;                  // 2

    float *lat, *Kf, *Vf, *Qf, *Of;
    cudaGetSymbolAddress((void**)&lat, g_lat);
    cudaGetSymbolAddress((void**)&Kf,  g_K);
    cudaGetSymbolAddress((void**)&Vf,  g_V);
    cudaGetSymbolAddress((void**)&Qf,  g_Q);
    cudaGetSymbolAddress((void**)&Of,  g_O);

    const int attn_smem = (128 * AP + 64 * AP + 64 * AP + 128 * AP) * (int)sizeof(float);
    cudaFuncSetAttribute(attn_kernel, cudaFuncAttributeMaxDynamicSharedMemorySize,
                         attn_smem);

    // 1. lat = x @ W_kv
    lat_kernel<<<BT / 32, 256>>>(x, W_kv, lat);

    // 2. K,V = lat @ W_k / W_v
    kv_kernel<<<BT / 4, 256>>>(lat, W_k, W_v, Kf, Vf);

    // 3. Q = x @ W_q  (tf32 mma)
    dim3 gq(D_MODEL / 128, BT / 128);
    gemm_tf32<<<gq, 256>>>(x, W_q, Qf, BT, D_MODEL, D_MODEL);

    // 4. causal flash attention (tf32 mma)
    dim3 ga(T / 128, B * N_HEADS);
    attn_kernel<<<ga, 256, attn_smem>>>(Qf, Kf, Vf, Of, T);

    // 5. out = O @ W_o  (tf32 mma)
    gemm_tf32<<<gq, 256>>>(Of, W_o, out, BT, D_MODEL, D_MODEL);
}